// round 16
// baseline (speedup 1.0000x reference)
#include <cuda_runtime.h>
#include <cuda_fp16.h>
#include <cstdint>
#include <cstddef>

// ---------------------------------------------------------------------------
// QuantizedLinear: out[M,N] = x[M,K] @ (wq*scale)[N,K]^T + bias
// M = 16384, K = 4096, N = 16384, fp32 I/O.  SIMT mma.sync (HMMA) path.
// Numerics: single-pass fp16 (validated twice: rel_err 2.09e-4).
// R14: CTA tile 128x128 -> 128x256 (8 warps, 64x64 warp tiles, 1 CTA/SM)
//      to cut SMEM-fill traffic 25% (0.0305 -> 0.0229 B/MAC) and halve
//      per-SM cp.async issue; preps fused into ONE kernel (also aligns
//      ncu skip-5 onto the GEMM launch).
// ---------------------------------------------------------------------------

#define MTOT 16384
#define NTOT 16384
#define KTOT 4096

#define BM 128
#define BN 256
#define BK 64
#define NKSTEP (KTOT / BK)   // 64
#define STAGES 3
#define THREADS 256

// SMEM layout
#define SM_SCALE 0           // 256 f32
#define SM_BIAS  1024        // 256 f32
#define SM_BUF   2048
#define A_OFF    0           // 128 rows x 128B
#define B_OFF    16384       // 256 rows x 128B
#define STAGE_BYTES 49152
#define SMEM_TOTAL (SM_BUF + STAGES * STAGE_BYTES)   // 149504 -> 1 CTA/SM

// -------------------- scratch ----------------------------------------------
__device__ __half g_xh[(size_t)MTOT * KTOT];
__device__ __half g_w [(size_t)NTOT * KTOT];

// -------------------- PTX helpers ------------------------------------------
__device__ __forceinline__ uint32_t smem_u32(const void* p) {
    uint32_t a;
    asm("{ .reg .u64 t; cvta.to.shared.u64 t, %1; cvt.u32.u64 %0, t; }" : "=r"(a) : "l"(p));
    return a;
}
#define CP_ASYNC16(dst, src) \
    asm volatile("cp.async.cg.shared.global [%0], [%1], 16;" :: "r"(dst), "l"(src) : "memory")
#define CP_COMMIT() asm volatile("cp.async.commit_group;" ::: "memory")
#define CP_WAIT(n)  asm volatile("cp.async.wait_group %0;" :: "n"(n) : "memory")

__device__ __forceinline__ void ldsm_x4(uint32_t& r0, uint32_t& r1, uint32_t& r2, uint32_t& r3,
                                        uint32_t a) {
    asm volatile("ldmatrix.sync.aligned.m8n8.x4.shared.b16 {%0,%1,%2,%3}, [%4];"
                 : "=r"(r0), "=r"(r1), "=r"(r2), "=r"(r3) : "r"(a));
}
__device__ __forceinline__ void mma_f16(float* d, const uint32_t* a, const uint32_t* b) {
    asm volatile("mma.sync.aligned.m16n8k16.row.col.f32.f16.f16.f32 "
                 "{%0,%1,%2,%3}, {%4,%5,%6,%7}, {%8,%9}, {%0,%1,%2,%3};"
                 : "+f"(d[0]), "+f"(d[1]), "+f"(d[2]), "+f"(d[3])
                 : "r"(a[0]), "r"(a[1]), "r"(a[2]), "r"(a[3]), "r"(b[0]), "r"(b[1]));
}
__device__ __forceinline__ uint32_t sw128(uint32_t o) { return o ^ ((o >> 3) & 0x70); }

// -------------------- fused prep kernel ------------------------------------
// First 65536 blocks: W int32 -> fp16.  Last 65536 blocks: x fp32 -> fp16.
// One kernel per replay => launch sequence (prep, gemm)* so ncu -s 5 lands
// on the GEMM.
__global__ void prep_kernel(const float* __restrict__ x, const int* __restrict__ wq) {
    size_t i = (size_t)blockIdx.x * blockDim.x + threadIdx.x;  // 4 elems each
    const size_t HALF = (size_t)65536 * 256;
    if (i < HALF) {
        int4 v = reinterpret_cast<const int4*>(wq)[i];
        union { __half h[4]; uint2 u; } r;
        r.h[0] = __int2half_rn(v.x);
        r.h[1] = __int2half_rn(v.y);
        r.h[2] = __int2half_rn(v.z);
        r.h[3] = __int2half_rn(v.w);
        reinterpret_cast<uint2*>(g_w)[i] = r.u;
    } else {
        size_t j = i - HALF;
        float4 v = reinterpret_cast<const float4*>(x)[j];
        union { __half h[4]; uint2 u; } r;
        r.h[0] = __float2half_rn(v.x);
        r.h[1] = __float2half_rn(v.y);
        r.h[2] = __float2half_rn(v.z);
        r.h[3] = __float2half_rn(v.w);
        reinterpret_cast<uint2*>(g_xh)[j] = r.u;
    }
}

// -------------------- GEMM kernel ------------------------------------------
__global__ __launch_bounds__(THREADS, 1)
void gemm_kernel(const float* __restrict__ scale, const float* __restrict__ bias,
                 float* __restrict__ out) {
    extern __shared__ __align__(1024) char smem[];
    const uint32_t sb = smem_u32(smem);
    const int tid  = threadIdx.x;
    const int wid  = tid >> 5;
    const int lane = tid & 31;

    // rasterize: groups of 8 M-tiles sweep all 64 N-tiles (L2 reuse of B)
    const int bid = blockIdx.x;
    const int grp = bid >> 9;          // /(8*64)
    const int r   = bid & 511;
    const int mt  = (grp << 3) + (r & 7);
    const int nt  = r >> 3;            // 0..63

    const char* pa = (const char*)g_xh + (size_t)mt * BM * (KTOT * 2);
    const char* pb = (const char*)g_w  + (size_t)nt * BN * (KTOT * 2);

    // per-thread cp.async addressing: 256 threads, seg = 16B segment,
    // rb = tid>>3 (0..31); A rows rb+32j (j<4), B rows rb+32j (j<8)
    const int seg = tid & 7;
    const int rb  = tid >> 3;
    uint32_t smoffA[4], smoffB[8];
    size_t   goffA[4], goffB[8];
#pragma unroll
    for (int j = 0; j < 4; j++) {
        int row = rb + 32 * j;
        smoffA[j] = sw128((uint32_t)(row * 128 + seg * 16));
        goffA[j]  = (size_t)row * (KTOT * 2) + seg * 16;
    }
#pragma unroll
    for (int j = 0; j < 8; j++) {
        int row = rb + 32 * j;
        smoffB[j] = sw128((uint32_t)(row * 128 + seg * 16));
        goffB[j]  = (size_t)row * (KTOT * 2) + seg * 16;
    }

    float* s_scale = reinterpret_cast<float*>(smem + SM_SCALE);
    float* s_bias  = reinterpret_cast<float*>(smem + SM_BIAS);
    s_scale[tid] = scale[nt * BN + tid];
    s_bias[tid]  = bias[nt * BN + tid];

    // prologue: stages 0..1
#pragma unroll
    for (int s = 0; s < STAGES - 1; s++) {
        const uint32_t sa = sb + SM_BUF + s * STAGE_BYTES;
        const size_t kofs = (size_t)s * (BK * 2);
#pragma unroll
        for (int j = 0; j < 4; j++)
            CP_ASYNC16(sa + A_OFF + smoffA[j], pa + goffA[j] + kofs);
#pragma unroll
        for (int j = 0; j < 8; j++)
            CP_ASYNC16(sa + B_OFF + smoffB[j], pb + goffB[j] + kofs);
        CP_COMMIT();
    }

    // warp tiling: 2 (M) x 4 (N); warp tile 64x64
    const int m_off = (wid >> 2) * 64;
    const int n_off = (wid & 3) * 64;

    // A ldmatrix.x4 lane selectors (m16 x k16 fragment)
    const int aRow  = lane & 15;
    const int aCol8 = ((lane >> 4) & 1) * 8;               // k half
    // B ldmatrix.x4: {n8 lo-k, n8 hi-k, (n+8) lo-k, (n+8) hi-k}
    const int bRow  = (lane & 7) + ((lane >> 4) & 1) * 8;  // row within 16-row pair
    const int bCol  = ((lane >> 3) & 1) * 16;              // k-half byte offset

    float acc[4][8][4];
#pragma unroll
    for (int im = 0; im < 4; im++)
#pragma unroll
        for (int jn = 0; jn < 8; jn++)
#pragma unroll
            for (int q = 0; q < 4; q++) acc[im][jn][q] = 0.0f;

#pragma unroll 1
    for (int ks = 0; ks < NKSTEP; ks++) {
        CP_WAIT(1);              // stage ks resident (1 group may remain in flight)
        __syncthreads();         // all warps done with stage (ks-1)%3

        // issue load for stage ks+2 (overwrites stage (ks-1)%3)
        if (ks + STAGES - 1 < NKSTEP) {
            const uint32_t sa = sb + SM_BUF + ((ks + STAGES - 1) % STAGES) * STAGE_BYTES;
            const size_t kofs = (size_t)(ks + STAGES - 1) * (BK * 2);
#pragma unroll
            for (int j = 0; j < 4; j++)
                CP_ASYNC16(sa + A_OFF + smoffA[j], pa + goffA[j] + kofs);
#pragma unroll
            for (int j = 0; j < 8; j++)
                CP_ASYNC16(sa + B_OFF + smoffB[j], pb + goffB[j] + kofs);
        }
        CP_COMMIT();             // commit every iter to keep group count aligned

        const uint32_t sa = sb + SM_BUF + (ks % STAGES) * STAGE_BYTES;
#pragma unroll
        for (int kk = 0; kk < 4; kk++) {           // 4 k-steps of 16 within BK=64
            const int colA = kk * 32 + aCol8 * 2;
            const int colB = kk * 32 + bCol;

            uint32_t af[4][4], bf[8][2];
#pragma unroll
            for (int im = 0; im < 4; im++) {
                int row = m_off + im * 16 + aRow;
                uint32_t off = sw128((uint32_t)(row * 128 + colA));
                ldsm_x4(af[im][0], af[im][1], af[im][2], af[im][3], sa + A_OFF + off);
            }
#pragma unroll
            for (int jp = 0; jp < 4; jp++) {       // pairs of n8 tiles (16 rows)
                int row = n_off + jp * 16 + bRow;
                uint32_t off = sw128((uint32_t)(row * 128 + colB));
                ldsm_x4(bf[jp * 2][0], bf[jp * 2][1], bf[jp * 2 + 1][0], bf[jp * 2 + 1][1],
                        sa + B_OFF + off);
            }
#pragma unroll
            for (int im = 0; im < 4; im++)
#pragma unroll
                for (int jn = 0; jn < 8; jn++)
                    mma_f16(acc[im][jn], af[im], bf[jn]);
        }
    }
    CP_WAIT(0);
    __syncthreads();

    // ---------------- epilogue: scale/bias + store (float2) ----------------
    const int dRow = lane >> 2;          // 0..7
    const int dCol = (lane & 3) * 2;     // 0,2,4,6
    const size_t obase = (size_t)(mt * BM) * NTOT + (size_t)nt * BN;

#pragma unroll
    for (int im = 0; im < 4; im++) {
#pragma unroll
        for (int jn = 0; jn < 8; jn++) {
            const int c  = n_off + jn * 8 + dCol;
            const float s0 = s_scale[c],     b0 = s_bias[c];
            const float s1 = s_scale[c + 1], b1 = s_bias[c + 1];
            const int r0 = m_off + im * 16 + dRow;
            float2 v0 = make_float2(acc[im][jn][0] * s0 + b0, acc[im][jn][1] * s1 + b1);
            float2 v1 = make_float2(acc[im][jn][2] * s0 + b0, acc[im][jn][3] * s1 + b1);
            *reinterpret_cast<float2*>(out + obase + (size_t)r0 * NTOT + c)       = v0;
            *reinterpret_cast<float2*>(out + obase + (size_t)(r0 + 8) * NTOT + c) = v1;
        }
    }
}

// -------------------- launch ------------------------------------------------
extern "C" void kernel_launch(void* const* d_in, const int* in_sizes, int n_in,
                              void* d_out, int out_size) {
    (void)in_sizes; (void)n_in; (void)out_size;
    const float* x    = (const float*)d_in[0];
    const int*   wq   = (const int*)d_in[1];
    const float* wsc  = (const float*)d_in[2];
    const float* bias = (const float*)d_in[3];
    float*       out  = (float*)d_out;

    cudaFuncSetAttribute(gemm_kernel, cudaFuncAttributeMaxDynamicSharedMemorySize, SMEM_TOTAL);

    // fused prep: first half W, second half x (4 elems/thread each)
    prep_kernel<<<131072, 256>>>(x, wq);

    // 128 M-tiles x 64 N-tiles = 8192 CTAs
    gemm_kernel<<<8192, THREADS, SMEM_TOTAL>>>(wsc, bias, out);
}

// round 17
// speedup vs baseline: 1.1309x; 1.1309x over previous
#include <cuda_runtime.h>
#include <cuda_fp16.h>
#include <cstdint>
#include <cstddef>

// ---------------------------------------------------------------------------
// QuantizedLinear: out[M,N] = x[M,K] @ (wq*scale)[N,K]^T + bias
// M = 16384, K = 4096, N = 16384, fp32 I/O.  SIMT mma.sync (HMMA) path.
// Numerics: single-pass fp16 (validated 3x: rel_err 2.09e-4).
// R17: REVERT GEMM to R13 config (128x128 CTA, 4 warps of 64x64, 3 stages,
//      2 CTAs/SM) — R16 proved 2-CTA alternation beats bigger tiles at the
//      8-warp/SM cap imposed by 237 regs. Keep R16's fused prep (1 launch,
//      ~65us) and the (prep,gemm)* pattern so ncu -s 5 profiles the GEMM.
// ---------------------------------------------------------------------------

#define MTOT 16384
#define NTOT 16384
#define KTOT 4096

#define BM 128
#define BN 128
#define BK 64
#define NKSTEP (KTOT / BK)   // 64
#define STAGES 3
#define THREADS 128

// SMEM layout
#define SM_SCALE 0           // 128 f32
#define SM_BIAS  512         // 128 f32
#define SM_BUF   1024
#define A_OFF    0           // 128 rows x 128B (fp16, BK=64)
#define B_OFF    16384
#define STAGE_BYTES 32768
#define SMEM_TOTAL (SM_BUF + STAGES * STAGE_BYTES)   // 99328 -> 2 CTAs/SM

// -------------------- scratch ----------------------------------------------
__device__ __half g_xh[(size_t)MTOT * KTOT];
__device__ __half g_w [(size_t)NTOT * KTOT];

// -------------------- PTX helpers ------------------------------------------
__device__ __forceinline__ uint32_t smem_u32(const void* p) {
    uint32_t a;
    asm("{ .reg .u64 t; cvta.to.shared.u64 t, %1; cvt.u32.u64 %0, t; }" : "=r"(a) : "l"(p));
    return a;
}
#define CP_ASYNC16(dst, src) \
    asm volatile("cp.async.cg.shared.global [%0], [%1], 16;" :: "r"(dst), "l"(src) : "memory")
#define CP_COMMIT() asm volatile("cp.async.commit_group;" ::: "memory")
#define CP_WAIT(n)  asm volatile("cp.async.wait_group %0;" :: "n"(n) : "memory")

__device__ __forceinline__ void ldsm_x4(uint32_t& r0, uint32_t& r1, uint32_t& r2, uint32_t& r3,
                                        uint32_t a) {
    asm volatile("ldmatrix.sync.aligned.m8n8.x4.shared.b16 {%0,%1,%2,%3}, [%4];"
                 : "=r"(r0), "=r"(r1), "=r"(r2), "=r"(r3) : "r"(a));
}
__device__ __forceinline__ void mma_f16(float* d, const uint32_t* a, const uint32_t* b) {
    asm volatile("mma.sync.aligned.m16n8k16.row.col.f32.f16.f16.f32 "
                 "{%0,%1,%2,%3}, {%4,%5,%6,%7}, {%8,%9}, {%0,%1,%2,%3};"
                 : "+f"(d[0]), "+f"(d[1]), "+f"(d[2]), "+f"(d[3])
                 : "r"(a[0]), "r"(a[1]), "r"(a[2]), "r"(a[3]), "r"(b[0]), "r"(b[1]));
}
__device__ __forceinline__ uint32_t sw128(uint32_t o) { return o ^ ((o >> 3) & 0x70); }

// -------------------- fused prep kernel ------------------------------------
// First 65536 blocks: W int32 -> fp16.  Last 65536 blocks: x fp32 -> fp16.
// One kernel per replay => launch sequence (prep, gemm)* so ncu -s 5 lands
// on the GEMM.
__global__ void prep_kernel(const float* __restrict__ x, const int* __restrict__ wq) {
    size_t i = (size_t)blockIdx.x * blockDim.x + threadIdx.x;  // 4 elems each
    const size_t HALF = (size_t)65536 * 256;
    if (i < HALF) {
        int4 v = reinterpret_cast<const int4*>(wq)[i];
        union { __half h[4]; uint2 u; } r;
        r.h[0] = __int2half_rn(v.x);
        r.h[1] = __int2half_rn(v.y);
        r.h[2] = __int2half_rn(v.z);
        r.h[3] = __int2half_rn(v.w);
        reinterpret_cast<uint2*>(g_w)[i] = r.u;
    } else {
        size_t j = i - HALF;
        float4 v = reinterpret_cast<const float4*>(x)[j];
        union { __half h[4]; uint2 u; } r;
        r.h[0] = __float2half_rn(v.x);
        r.h[1] = __float2half_rn(v.y);
        r.h[2] = __float2half_rn(v.z);
        r.h[3] = __float2half_rn(v.w);
        reinterpret_cast<uint2*>(g_xh)[j] = r.u;
    }
}

// -------------------- GEMM kernel (R13 config) ------------------------------
__global__ __launch_bounds__(THREADS, 2)
void gemm_kernel(const float* __restrict__ scale, const float* __restrict__ bias,
                 float* __restrict__ out) {
    extern __shared__ __align__(1024) char smem[];
    const uint32_t sb = smem_u32(smem);
    const int tid  = threadIdx.x;
    const int wid  = tid >> 5;
    const int lane = tid & 31;

    // rasterize: groups of 8 M-tiles sweep all 128 N-tiles (L2 reuse of B)
    const int bid = blockIdx.x;
    const int grp = bid >> 10;
    const int r   = bid & 1023;
    const int mt  = (grp << 3) + (r & 7);
    const int nt  = r >> 3;

    const char* pa = (const char*)g_xh + (size_t)mt * BM * (KTOT * 2);
    const char* pb = (const char*)g_w  + (size_t)nt * BN * (KTOT * 2);

    // per-thread cp.async addressing: 128 threads, seg = 16B segment,
    // rows rb+16j (j=0..7) -> 8 A + 8 B cp.async per thread per stage
    const int seg = tid & 7;
    const int rb  = tid >> 3;      // 0..15
    uint32_t smoff[8];
    size_t   goff[8];
#pragma unroll
    for (int j = 0; j < 8; j++) {
        int row = rb + 16 * j;
        smoff[j] = sw128((uint32_t)(row * 128 + seg * 16));
        goff[j]  = (size_t)row * (KTOT * 2) + seg * 16;
    }

    float* s_scale = reinterpret_cast<float*>(smem + SM_SCALE);
    float* s_bias  = reinterpret_cast<float*>(smem + SM_BIAS);
    s_scale[tid] = scale[nt * BN + tid];
    s_bias[tid]  = bias[nt * BN + tid];

    // prologue: stages 0..1
#pragma unroll
    for (int s = 0; s < STAGES - 1; s++) {
        const uint32_t sa = sb + SM_BUF + s * STAGE_BYTES;
        const size_t kofs = (size_t)s * (BK * 2);
#pragma unroll
        for (int j = 0; j < 8; j++) {
            CP_ASYNC16(sa + A_OFF + smoff[j], pa + goff[j] + kofs);
            CP_ASYNC16(sa + B_OFF + smoff[j], pb + goff[j] + kofs);
        }
        CP_COMMIT();
    }

    // warp tiling: 2 (M) x 2 (N); warp tile 64x64
    const int m_off = (wid >> 1) * 64;
    const int n_off = (wid & 1) * 64;

    // A ldmatrix.x4 lane selectors (m16 x k16 fragment)
    const int aRow  = lane & 15;
    const int aCol8 = ((lane >> 4) & 1) * 8;               // k half
    // B ldmatrix.x4: {n8 lo-k, n8 hi-k, (n+8) lo-k, (n+8) hi-k}
    const int bRow  = (lane & 7) + ((lane >> 4) & 1) * 8;  // row within 16-row pair
    const int bCol  = ((lane >> 3) & 1) * 16;              // k-half byte offset

    float acc[4][8][4];
#pragma unroll
    for (int im = 0; im < 4; im++)
#pragma unroll
        for (int jn = 0; jn < 8; jn++)
#pragma unroll
            for (int q = 0; q < 4; q++) acc[im][jn][q] = 0.0f;

#pragma unroll 1
    for (int ks = 0; ks < NKSTEP; ks++) {
        CP_WAIT(1);              // stage ks resident (1 group may remain in flight)
        __syncthreads();         // all warps done with stage (ks-1)%3

        // issue load for stage ks+2 (overwrites stage (ks-1)%3)
        if (ks + STAGES - 1 < NKSTEP) {
            const uint32_t sa = sb + SM_BUF + ((ks + STAGES - 1) % STAGES) * STAGE_BYTES;
            const size_t kofs = (size_t)(ks + STAGES - 1) * (BK * 2);
#pragma unroll
            for (int j = 0; j < 8; j++) {
                CP_ASYNC16(sa + A_OFF + smoff[j], pa + goff[j] + kofs);
                CP_ASYNC16(sa + B_OFF + smoff[j], pb + goff[j] + kofs);
            }
        }
        CP_COMMIT();             // commit every iter to keep group count aligned

        const uint32_t sa = sb + SM_BUF + (ks % STAGES) * STAGE_BYTES;
#pragma unroll
        for (int kk = 0; kk < 4; kk++) {           // 4 k-steps of 16 within BK=64
            const int colA = kk * 32 + aCol8 * 2;
            const int colB = kk * 32 + bCol;

            uint32_t af[4][4], bf[8][2];
#pragma unroll
            for (int im = 0; im < 4; im++) {
                int row = m_off + im * 16 + aRow;
                uint32_t off = sw128((uint32_t)(row * 128 + colA));
                ldsm_x4(af[im][0], af[im][1], af[im][2], af[im][3], sa + A_OFF + off);
            }
#pragma unroll
            for (int jp = 0; jp < 4; jp++) {       // pairs of n8 tiles (16 rows)
                int row = n_off + jp * 16 + bRow;
                uint32_t off = sw128((uint32_t)(row * 128 + colB));
                ldsm_x4(bf[jp * 2][0], bf[jp * 2][1], bf[jp * 2 + 1][0], bf[jp * 2 + 1][1],
                        sa + B_OFF + off);
            }
#pragma unroll
            for (int im = 0; im < 4; im++)
#pragma unroll
                for (int jn = 0; jn < 8; jn++)
                    mma_f16(acc[im][jn], af[im], bf[jn]);
        }
    }
    CP_WAIT(0);
    __syncthreads();

    // ---------------- epilogue: scale/bias + store (float2) ----------------
    const int dRow = lane >> 2;          // 0..7
    const int dCol = (lane & 3) * 2;     // 0,2,4,6
    const size_t obase = (size_t)(mt * BM) * NTOT + (size_t)nt * BN;

#pragma unroll
    for (int im = 0; im < 4; im++) {
#pragma unroll
        for (int jn = 0; jn < 8; jn++) {
            const int c  = n_off + jn * 8 + dCol;
            const float s0 = s_scale[c],     b0 = s_bias[c];
            const float s1 = s_scale[c + 1], b1 = s_bias[c + 1];
            const int r0 = m_off + im * 16 + dRow;
            float2 v0 = make_float2(acc[im][jn][0] * s0 + b0, acc[im][jn][1] * s1 + b1);
            float2 v1 = make_float2(acc[im][jn][2] * s0 + b0, acc[im][jn][3] * s1 + b1);
            *reinterpret_cast<float2*>(out + obase + (size_t)r0 * NTOT + c)       = v0;
            *reinterpret_cast<float2*>(out + obase + (size_t)(r0 + 8) * NTOT + c) = v1;
        }
    }
}

// -------------------- launch ------------------------------------------------
extern "C" void kernel_launch(void* const* d_in, const int* in_sizes, int n_in,
                              void* d_out, int out_size) {
    (void)in_sizes; (void)n_in; (void)out_size;
    const float* x    = (const float*)d_in[0];
    const int*   wq   = (const int*)d_in[1];
    const float* wsc  = (const float*)d_in[2];
    const float* bias = (const float*)d_in[3];
    float*       out  = (float*)d_out;

    cudaFuncSetAttribute(gemm_kernel, cudaFuncAttributeMaxDynamicSharedMemorySize, SMEM_TOTAL);

    // fused prep: first half W, second half x (4 elems/thread each)
    prep_kernel<<<131072, 256>>>(x, wq);

    // (16384/128)^2 = 16384 tiles
    gemm_kernel<<<16384, THREADS, SMEM_TOTAL>>>(wsc, bias, out);
}